// round 1
// baseline (speedup 1.0000x reference)
#include <cuda_runtime.h>

#define D   128
#define DP  132          // padded smem row stride (conflict-free float4 access)
#define MAXN 100000

// Scratch (allocation-free: __device__ globals)
__device__ float g_h[(size_t)MAXN * D];   // x @ W^T
__device__ float g_deg[MAXN];
__device__ float g_dinv[MAXN];

// ---------------------------------------------------------------------------
// Degree (with self-loop) and deg^-1/2
// ---------------------------------------------------------------------------
__global__ void k_deg_init(int n) {
    int i = blockIdx.x * blockDim.x + threadIdx.x;
    if (i < n) g_deg[i] = 1.0f;   // self loop
}

__global__ void k_deg_edge(const int* __restrict__ dst, int e) {
    int i = blockIdx.x * blockDim.x + threadIdx.x;
    if (i < e) atomicAdd(&g_deg[dst[i]], 1.0f);
}

__global__ void k_dinv(int n) {
    int i = blockIdx.x * blockDim.x + threadIdx.x;
    if (i < n) g_dinv[i] = rsqrtf(g_deg[i]);
}

// ---------------------------------------------------------------------------
// h = x @ W^T    (W row-major [c][k]; h[n][c] = sum_k x[n][k] * W[c][k])
// Block: 256 threads, tile 32 rows x 128 cols.
// Thread = 1 output col x 16 rows. W row for this col is K-contiguous -> float4.
// x-row loads are warp-uniform broadcasts; W loads conflict-free (DP pad).
// Stores: lane varies col -> fully coalesced.
// ---------------------------------------------------------------------------
__launch_bounds__(256, 2)
__global__ void k_gemm(const float* __restrict__ x, const float* __restrict__ W, int n) {
    __shared__ float ws[D * DP];    // ws[c*DP + k] = W[c][k]
    __shared__ float xs[32 * DP];   // xs[r*DP + k]
    int tid = threadIdx.x;
    int row0 = blockIdx.x * 32;

    // Load W (64KB) coalesced, same [c][k] layout, padded rows
    for (int i4 = tid; i4 < D * D / 4; i4 += 256) {
        int c = i4 >> 5, kq = i4 & 31;
        float4 v = ((const float4*)W)[i4];
        *(float4*)(ws + c * DP + kq * 4) = v;
    }
    // Load x tile (32 rows)
    for (int i4 = tid; i4 < 32 * D / 4; i4 += 256) {
        int r = i4 >> 5, kq = i4 & 31;
        int row = row0 + r;
        float4 v = make_float4(0.f, 0.f, 0.f, 0.f);
        if (row < n) v = ((const float4*)(x + (size_t)row * D))[kq];
        *(float4*)(xs + r * DP + kq * 4) = v;
    }
    __syncthreads();

    int lane = tid & 31;
    int g    = tid >> 5;
    int c    = (g & 3) * 32 + lane;   // output column
    int r0   = (g >> 2) * 16;         // 16-row group
    const float* wrow = ws + c * DP;

    float acc[16];
    #pragma unroll
    for (int r = 0; r < 16; r++) acc[r] = 0.0f;

    #pragma unroll 2
    for (int k = 0; k < D; k += 4) {
        float4 w = *(const float4*)(wrow + k);
        #pragma unroll
        for (int r = 0; r < 16; r++) {
            float4 a = *(const float4*)(xs + (r0 + r) * DP + k);
            acc[r] += a.x * w.x + a.y * w.y + a.z * w.z + a.w * w.w;
        }
    }

    #pragma unroll
    for (int r = 0; r < 16; r++) {
        int row = row0 + r0 + r;
        if (row < n) g_h[(size_t)row * D + c] = acc[r];
    }
}

// ---------------------------------------------------------------------------
// out[i] = h[i] * dinv[i]^2 (self loop) + b    (writes every element of d_out)
// ---------------------------------------------------------------------------
__global__ void k_init_out(const float* __restrict__ b, float* __restrict__ out, int n) {
    int i = blockIdx.x * blockDim.x + threadIdx.x;   // over n*32 float4s
    if (i >= n * 32) return;
    int node = i >> 5, cq = i & 31;
    float di = g_dinv[node];
    float s  = di * di;
    float4 hv = ((const float4*)g_h)[i];
    float4 bv = ((const float4*)b)[cq];
    float4 o;
    o.x = hv.x * s + bv.x;
    o.y = hv.y * s + bv.y;
    o.z = hv.z * s + bv.z;
    o.w = hv.w * s + bv.w;
    ((float4*)out)[i] = o;
}

// ---------------------------------------------------------------------------
// Edge scatter: warp per edge. Coalesced float4 gather of h[src] (L2-resident),
// vectorized reduction into out[dst] (red.global.add.v4.f32, sm_90+).
// ---------------------------------------------------------------------------
__device__ __forceinline__ void red_add_v4(float* p, float x, float y, float z, float w) {
    asm volatile("red.global.add.v4.f32 [%0], {%1, %2, %3, %4};"
                 :: "l"(p), "f"(x), "f"(y), "f"(z), "f"(w) : "memory");
}

__global__ void k_scatter(const int* __restrict__ src, const int* __restrict__ dst,
                          float* __restrict__ out, int e) {
    int widx = (blockIdx.x * blockDim.x + threadIdx.x) >> 5;
    int lane = threadIdx.x & 31;
    if (widx >= e) return;
    int s = __ldg(src + widx);
    int d = __ldg(dst + widx);
    float norm = g_dinv[s] * g_dinv[d];
    float4 v = ((const float4*)(g_h + (size_t)s * D))[lane];
    red_add_v4(out + (size_t)d * D + lane * 4,
               v.x * norm, v.y * norm, v.z * norm, v.w * norm);
}

// ---------------------------------------------------------------------------
// PReLU (single learnable slope)
// ---------------------------------------------------------------------------
__global__ void k_prelu(float* __restrict__ out, const float* __restrict__ a, int n4) {
    int i = blockIdx.x * blockDim.x + threadIdx.x;
    if (i >= n4) return;
    float slope = a[0];
    float4 v = ((float4*)out)[i];
    v.x = v.x >= 0.f ? v.x : slope * v.x;
    v.y = v.y >= 0.f ? v.y : slope * v.y;
    v.z = v.z >= 0.f ? v.z : slope * v.z;
    v.w = v.w >= 0.f ? v.w : slope * v.w;
    ((float4*)out)[i] = v;
}

// ---------------------------------------------------------------------------
extern "C" void kernel_launch(void* const* d_in, const int* in_sizes, int n_in,
                              void* d_out, int out_size) {
    const float* x  = (const float*)d_in[0];
    const int*   ei = (const int*)d_in[1];     // [2, E] row-major
    const float* W  = (const float*)d_in[2];
    const float* b  = (const float*)d_in[3];
    const float* a  = (const float*)d_in[4];
    float* out = (float*)d_out;

    int n = in_sizes[0] / D;
    int e = in_sizes[1] / 2;
    const int* src = ei;
    const int* dst = ei + e;

    int nb256  = (n + 255) / 256;
    int eb256  = (e + 255) / 256;

    k_deg_init<<<nb256, 256>>>(n);
    k_deg_edge<<<eb256, 256>>>(dst, e);
    k_dinv<<<nb256, 256>>>(n);

    k_gemm<<<(n + 31) / 32, 256>>>(x, W, n);

    int n4 = n * 32;                       // float4 count = n*D/4
    k_init_out<<<(n4 + 255) / 256, 256>>>(b, out, n);

    k_scatter<<<(e + 7) / 8, 256>>>(src, dst, out, e);   // 8 warps/block, warp/edge

    k_prelu<<<(n4 + 255) / 256, 256>>>(out, a, n4);
}

// round 2
// speedup vs baseline: 1.0084x; 1.0084x over previous
#include <cuda_runtime.h>
#include <cstdint>

#define D    128
#define MAXN 100000
#define MAXE 1600000

// ---------------- scratch (__device__ globals, allocation-free) -------------
__device__ float g_h[(size_t)MAXN * D];     // x @ W^T
__device__ float g_dinv[MAXN];
__device__ int   g_cnt[MAXN];               // in-degree histogram (no self loop)
__device__ int   g_off[MAXN + 1];           // CSR offsets
__device__ int   g_cur[MAXN];               // fill cursors
__device__ int   g_csr_src[MAXE];           // CSR adjacency (src per dst)

// ---------------------------------------------------------------------------
// 1) zero histogram
// ---------------------------------------------------------------------------
__global__ void k_zero(int n) {
    int i = blockIdx.x * blockDim.x + threadIdx.x;
    if (i < n) g_cnt[i] = 0;
}

// 2) histogram of dst (serves as degree and CSR counts)
__global__ void k_hist(const int* __restrict__ dst, int e) {
    int i = blockIdx.x * blockDim.x + threadIdx.x;
    if (i < e) atomicAdd(&g_cnt[dst[i]], 1);
}

// 3) single-block scan: g_off (exclusive), cursors, dinv = rsqrt(cnt+1)
__global__ void k_scan(int n, int e) {
    __shared__ int sums[1024];
    int t = threadIdx.x;
    int chunk = (n + 1023) / 1024;
    int beg = t * chunk;
    int end = beg + chunk; if (end > n) end = n;
    int s = 0;
    for (int i = beg; i < end; i++) s += g_cnt[i];
    sums[t] = s;
    __syncthreads();
    for (int off = 1; off < 1024; off <<= 1) {
        int v = (t >= off) ? sums[t - off] : 0;
        __syncthreads();
        sums[t] += v;
        __syncthreads();
    }
    int run = (t == 0) ? 0 : sums[t - 1];
    for (int i = beg; i < end; i++) {
        int c = g_cnt[i];
        g_off[i] = run;
        g_cur[i] = run;
        g_dinv[i] = rsqrtf((float)c + 1.0f);   // +1 = self loop
        run += c;
    }
    if (t == 0) g_off[n] = e;
}

// 4) fill CSR
__global__ void k_fill(const int* __restrict__ src, const int* __restrict__ dst, int e) {
    int i = blockIdx.x * blockDim.x + threadIdx.x;
    if (i < e) {
        int p = atomicAdd(&g_cur[dst[i]], 1);
        g_csr_src[p] = src[i];
    }
}

// ---------------------------------------------------------------------------
// 5) GEMM: h = x @ W^T via 3xTF32 mma.sync (fp32-class accuracy)
//    Block: 256 thr (8 warps), tile 128 rows x 128 cols, K chunked by 32.
//    Warp w -> rows w*16..w*16+15, iterates 16 n-tiles of 8 cols.
// ---------------------------------------------------------------------------
#define BK   32
#define SK   36   // padded k-stride: bank = (row*4 + k) & 31 -> conflict-free

__device__ __forceinline__ void tf32_split(float f, uint32_t& hi, uint32_t& lo) {
    uint32_t h;
    asm("cvt.rna.tf32.f32 %0, %1;" : "=r"(h) : "f"(f));
    float fl = f - __uint_as_float(h);
    uint32_t l;
    asm("cvt.rna.tf32.f32 %0, %1;" : "=r"(l) : "f"(fl));
    hi = h; lo = l;
}

__device__ __forceinline__ void mma_tf32(float* c, const uint32_t* a, const uint32_t* b) {
    asm volatile(
        "mma.sync.aligned.m16n8k8.row.col.f32.tf32.tf32.f32 "
        "{%0,%1,%2,%3}, {%4,%5,%6,%7}, {%8,%9}, {%0,%1,%2,%3};"
        : "+f"(c[0]), "+f"(c[1]), "+f"(c[2]), "+f"(c[3])
        : "r"(a[0]), "r"(a[1]), "r"(a[2]), "r"(a[3]), "r"(b[0]), "r"(b[1]));
}

__launch_bounds__(256, 1)
__global__ void k_gemm(const float* __restrict__ x, const float* __restrict__ W, int n) {
    __shared__ float xs[128 * SK];
    __shared__ float ws[128 * SK];

    int tid  = threadIdx.x;
    int lane = tid & 31;
    int wid  = tid >> 5;
    int grp  = lane >> 2;     // 0..7
    int tig  = lane & 3;      // 0..3
    int row0 = blockIdx.x * 128;
    int warpRow = wid * 16;

    float acc[16][4];
    #pragma unroll
    for (int nt = 0; nt < 16; nt++)
        #pragma unroll
        for (int i = 0; i < 4; i++) acc[nt][i] = 0.0f;

    for (int kc = 0; kc < D; kc += BK) {
        // load x tile (zero-padded rows) and W tile, coalesced float4
        #pragma unroll
        for (int it = 0; it < 4; it++) {
            int i4 = tid + it * 256;            // 1024 float4 total
            int r = i4 >> 3, q = i4 & 7;
            int row = row0 + r;
            float4 v = make_float4(0.f, 0.f, 0.f, 0.f);
            if (row < n) v = *(const float4*)(x + (size_t)row * D + kc + q * 4);
            *(float4*)(xs + r * SK + q * 4) = v;
            float4 wv = *(const float4*)(W + (size_t)r * D + kc + q * 4);
            *(float4*)(ws + r * SK + q * 4) = wv;
        }
        __syncthreads();

        #pragma unroll
        for (int ks = 0; ks < 4; ks++) {
            int k0 = ks * 8;
            uint32_t aH[4], aL[4];
            {
                float a0 = xs[(warpRow + grp)     * SK + k0 + tig];
                float a1 = xs[(warpRow + grp + 8) * SK + k0 + tig];
                float a2 = xs[(warpRow + grp)     * SK + k0 + tig + 4];
                float a3 = xs[(warpRow + grp + 8) * SK + k0 + tig + 4];
                tf32_split(a0, aH[0], aL[0]);
                tf32_split(a1, aH[1], aL[1]);
                tf32_split(a2, aH[2], aL[2]);
                tf32_split(a3, aH[3], aL[3]);
            }
            #pragma unroll
            for (int nt = 0; nt < 16; nt++) {
                int n0 = nt * 8;
                uint32_t bH[2], bL[2];
                float b0 = ws[(n0 + grp) * SK + k0 + tig];
                float b1 = ws[(n0 + grp) * SK + k0 + tig + 4];
                tf32_split(b0, bH[0], bL[0]);
                tf32_split(b1, bH[1], bL[1]);
                mma_tf32(acc[nt], aH, bH);
                mma_tf32(acc[nt], aH, bL);
                mma_tf32(acc[nt], aL, bH);
            }
        }
        __syncthreads();
    }

    // store: c0/c1 -> (row, n0+2t, +1); c2/c3 -> row+8
    #pragma unroll
    for (int nt = 0; nt < 16; nt++) {
        int n0 = nt * 8;
        int r1 = row0 + warpRow + grp;
        int r2 = r1 + 8;
        if (r1 < n) *(float2*)(g_h + (size_t)r1 * D + n0 + 2 * tig) =
            make_float2(acc[nt][0], acc[nt][1]);
        if (r2 < n) *(float2*)(g_h + (size_t)r2 * D + n0 + 2 * tig) =
            make_float2(acc[nt][2], acc[nt][3]);
    }
}

// ---------------------------------------------------------------------------
// 6) gather-aggregate: warp per node, fused self-loop + bias + PReLU
// ---------------------------------------------------------------------------
__launch_bounds__(256)
__global__ void k_agg(const float* __restrict__ b, const float* __restrict__ a,
                      float* __restrict__ out, int n) {
    int node = (blockIdx.x * blockDim.x + threadIdx.x) >> 5;
    int lane = threadIdx.x & 31;
    if (node >= n) return;

    float dd = g_dinv[node];
    float self = dd * dd;

    float4 hv = ((const float4*)(g_h + (size_t)node * D))[lane];
    float4 acc;
    acc.x = hv.x * self; acc.y = hv.y * self;
    acc.z = hv.z * self; acc.w = hv.w * self;

    int beg = g_off[node];
    int end = g_off[node + 1];

    int s_next = (beg < end) ? __ldg(g_csr_src + beg) : 0;
    for (int j = beg; j < end; j++) {
        int s = s_next;
        if (j + 1 < end) s_next = __ldg(g_csr_src + j + 1);
        float nm = __ldg(g_dinv + s) * dd;
        float4 v = ((const float4*)(g_h + (size_t)s * D))[lane];
        acc.x += v.x * nm; acc.y += v.y * nm;
        acc.z += v.z * nm; acc.w += v.w * nm;
    }

    float4 bv = ((const float4*)b)[lane];
    acc.x += bv.x; acc.y += bv.y; acc.z += bv.z; acc.w += bv.w;

    float slope = a[0];
    acc.x = acc.x >= 0.f ? acc.x : slope * acc.x;
    acc.y = acc.y >= 0.f ? acc.y : slope * acc.y;
    acc.z = acc.z >= 0.f ? acc.z : slope * acc.z;
    acc.w = acc.w >= 0.f ? acc.w : slope * acc.w;

    ((float4*)(out + (size_t)node * D))[lane] = acc;
}

// ---------------------------------------------------------------------------
extern "C" void kernel_launch(void* const* d_in, const int* in_sizes, int n_in,
                              void* d_out, int out_size) {
    const float* x  = (const float*)d_in[0];
    const int*   ei = (const int*)d_in[1];     // [2, E]
    const float* W  = (const float*)d_in[2];
    const float* b  = (const float*)d_in[3];
    const float* a  = (const float*)d_in[4];
    float* out = (float*)d_out;

    int n = in_sizes[0] / D;
    int e = in_sizes[1] / 2;
    const int* src = ei;
    const int* dst = ei + e;

    int nb = (n + 255) / 256;
    int eb = (e + 255) / 256;

    k_zero<<<nb, 256>>>(n);
    k_hist<<<eb, 256>>>(dst, e);
    k_scan<<<1, 1024>>>(n, e);
    k_fill<<<eb, 256>>>(src, dst, e);

    k_gemm<<<(n + 127) / 128, 256>>>(x, W, n);

    k_agg<<<(n * 32 + 255) / 256, 256>>>(b, a, out, n);
}

// round 3
// speedup vs baseline: 2.4621x; 2.4416x over previous
#include <cuda_runtime.h>
#include <cstdint>

#define D    128
#define SK   36            // padded smem k-stride: bank=(r*4+k)&31, conflict-free
#define MAXN 100000
#define MAXE 1600000
#define SCAN_B 1024

// ---------------- scratch (__device__ globals, allocation-free) -------------
__device__ float    g_h[(size_t)MAXN * D];
__device__ float    g_dinv[MAXN];
__device__ int      g_cnt[MAXN];
__device__ int      g_off[MAXN + 1];
__device__ int      g_cur[MAXN];
__device__ int2     g_csr[MAXE];          // {src, __float_as_int(dinv[src])}
__device__ int      g_bsum[SCAN_B];
__device__ int      g_bpre[SCAN_B];
__device__ uint32_t g_Whi[D * D];
__device__ uint32_t g_Wlo[D * D];

// ---------------------------------------------------------------------------
__device__ __forceinline__ void tf32_split(float f, uint32_t& hi, uint32_t& lo) {
    uint32_t h;
    asm("cvt.rna.tf32.f32 %0, %1;" : "=r"(h) : "f"(f));
    float fl = f - __uint_as_float(h);
    uint32_t l;
    asm("cvt.rna.tf32.f32 %0, %1;" : "=r"(l) : "f"(fl));
    hi = h; lo = l;
}

__device__ __forceinline__ void mma_tf32(float* c, const uint32_t* a, const uint32_t* b) {
    asm volatile(
        "mma.sync.aligned.m16n8k8.row.col.f32.tf32.tf32.f32 "
        "{%0,%1,%2,%3}, {%4,%5,%6,%7}, {%8,%9}, {%0,%1,%2,%3};"
        : "+f"(c[0]), "+f"(c[1]), "+f"(c[2]), "+f"(c[3])
        : "r"(a[0]), "r"(a[1]), "r"(a[2]), "r"(a[3]), "r"(b[0]), "r"(b[1]));
}

// ---------------------------------------------------------------------------
// 1) zero histogram + pre-split W into TF32 hi/lo (fused)
// ---------------------------------------------------------------------------
__global__ void k_pre(const float* __restrict__ W, int n) {
    int i = blockIdx.x * blockDim.x + threadIdx.x;
    if (i < n) g_cnt[i] = 0;
    if (i < D * D) {
        uint32_t hi, lo;
        tf32_split(W[i], hi, lo);
        g_Whi[i] = hi; g_Wlo[i] = lo;
    }
}

// 2) histogram of dst
__global__ void k_hist(const int* __restrict__ dst, int e) {
    int i = blockIdx.x * blockDim.x + threadIdx.x;
    if (i < e) atomicAdd(&g_cnt[dst[i]], 1);
}

// ---------------------------------------------------------------------------
// 3) multi-block scan: A) per-block exclusive + block sums (+dinv),
//                      B) scan block sums, C) fixup + cursors
// ---------------------------------------------------------------------------
__device__ __forceinline__ int block_incl_scan(int v, int* wsum) {
    int lane = threadIdx.x & 31, wid = threadIdx.x >> 5;
    int s = v;
    #pragma unroll
    for (int o = 1; o < 32; o <<= 1) {
        int t = __shfl_up_sync(0xffffffffu, s, o);
        if (lane >= o) s += t;
    }
    if (lane == 31) wsum[wid] = s;
    __syncthreads();
    if (wid == 0) {
        int ws = wsum[lane];
        #pragma unroll
        for (int o = 1; o < 32; o <<= 1) {
            int t = __shfl_up_sync(0xffffffffu, ws, o);
            if (lane >= o) ws += t;
        }
        wsum[lane] = ws;
    }
    __syncthreads();
    return s + (wid > 0 ? wsum[wid - 1] : 0);
}

__global__ void k_scanA(int n) {
    __shared__ int wsum[32];
    int i = blockIdx.x * 1024 + threadIdx.x;
    int v = (i < n) ? g_cnt[i] : 0;
    int incl = block_incl_scan(v, wsum);
    if (i < n) {
        g_off[i]  = incl - v;                       // exclusive within block
        g_dinv[i] = rsqrtf((float)v + 1.0f);        // +1 self loop
    }
    if (threadIdx.x == 1023) g_bsum[blockIdx.x] = incl;
}

__global__ void k_scanB(int nb) {
    __shared__ int wsum[32];
    int t = threadIdx.x;
    int v = (t < nb) ? g_bsum[t] : 0;
    int incl = block_incl_scan(v, wsum);
    if (t < nb) g_bpre[t] = incl - v;
}

__global__ void k_scanC(int n, int e) {
    int i = blockIdx.x * 1024 + threadIdx.x;
    if (i < n) {
        int o = g_off[i] + g_bpre[blockIdx.x];
        g_off[i] = o;
        g_cur[i] = o;
    }
    if (i == 0) g_off[n] = e;
}

// 4) fill CSR with packed {src, dinv[src]}
__global__ void k_fill(const int* __restrict__ src, const int* __restrict__ dst, int e) {
    int i = blockIdx.x * blockDim.x + threadIdx.x;
    if (i < e) {
        int s = src[i];
        int p = atomicAdd(&g_cur[dst[i]], 1);
        g_csr[p] = make_int2(s, __float_as_int(__ldg(g_dinv + s)));
    }
}

// ---------------------------------------------------------------------------
// 5) GEMM: h = x @ W^T, 3xTF32 mma.sync; W pre-split in global memory.
//    Block 256 thr, tile 128x128, K chunked by 32. Dynamic smem (54KB).
// ---------------------------------------------------------------------------
__launch_bounds__(256)
__global__ void k_gemm(const float* __restrict__ x, int n) {
    extern __shared__ float smem[];
    float*    xs = smem;                                // 128*SK floats
    uint32_t* wh = (uint32_t*)(smem + 128 * SK);        // 128*SK u32
    uint32_t* wl = wh + 128 * SK;

    int tid  = threadIdx.x;
    int lane = tid & 31;
    int wid  = tid >> 5;
    int grp  = lane >> 2;
    int tig  = lane & 3;
    int row0 = blockIdx.x * 128;
    int warpRow = wid * 16;

    float acc[16][4];
    #pragma unroll
    for (int nt = 0; nt < 16; nt++)
        #pragma unroll
        for (int i = 0; i < 4; i++) acc[nt][i] = 0.0f;

    for (int kc = 0; kc < D; kc += 32) {
        #pragma unroll
        for (int it = 0; it < 4; it++) {
            int i4 = tid + it * 256;       // 1024 float4s per array
            int r = i4 >> 3, q = i4 & 7;
            int row = row0 + r;
            float4 v = make_float4(0.f, 0.f, 0.f, 0.f);
            if (row < n) v = *(const float4*)(x + (size_t)row * D + kc + q * 4);
            *(float4*)(xs + r * SK + q * 4) = v;
            *(uint4*)(wh + r * SK + q * 4) = *(const uint4*)(g_Whi + (size_t)r * D + kc + q * 4);
            *(uint4*)(wl + r * SK + q * 4) = *(const uint4*)(g_Wlo + (size_t)r * D + kc + q * 4);
        }
        __syncthreads();

        #pragma unroll
        for (int ks = 0; ks < 4; ks++) {
            int k0 = ks * 8;
            uint32_t aH[4], aL[4];
            tf32_split(xs[(warpRow + grp)     * SK + k0 + tig],     aH[0], aL[0]);
            tf32_split(xs[(warpRow + grp + 8) * SK + k0 + tig],     aH[1], aL[1]);
            tf32_split(xs[(warpRow + grp)     * SK + k0 + tig + 4], aH[2], aL[2]);
            tf32_split(xs[(warpRow + grp + 8) * SK + k0 + tig + 4], aH[3], aL[3]);
            #pragma unroll
            for (int nt = 0; nt < 16; nt++) {
                int n0 = nt * 8;
                uint32_t bH[2], bL[2];
                bH[0] = wh[(n0 + grp) * SK + k0 + tig];
                bH[1] = wh[(n0 + grp) * SK + k0 + tig + 4];
                bL[0] = wl[(n0 + grp) * SK + k0 + tig];
                bL[1] = wl[(n0 + grp) * SK + k0 + tig + 4];
                mma_tf32(acc[nt], aH, bH);
                mma_tf32(acc[nt], aL, bH);
                mma_tf32(acc[nt], aH, bL);
            }
        }
        __syncthreads();
    }

    #pragma unroll
    for (int nt = 0; nt < 16; nt++) {
        int n0 = nt * 8;
        int r1 = row0 + warpRow + grp;
        int r2 = r1 + 8;
        if (r1 < n) *(float2*)(g_h + (size_t)r1 * D + n0 + 2 * tig) =
            make_float2(acc[nt][0], acc[nt][1]);
        if (r2 < n) *(float2*)(g_h + (size_t)r2 * D + n0 + 2 * tig) =
            make_float2(acc[nt][2], acc[nt][3]);
    }
}

// ---------------------------------------------------------------------------
// 6) gather-aggregate: warp/node, x4 unrolled gathers (MLP=4),
//    fused self-loop + bias + PReLU
// ---------------------------------------------------------------------------
__launch_bounds__(256)
__global__ void k_agg(const float* __restrict__ b, const float* __restrict__ a,
                      float* __restrict__ out, int n) {
    int node = (blockIdx.x * blockDim.x + threadIdx.x) >> 5;
    int lane = threadIdx.x & 31;
    if (node >= n) return;

    const float4* hb = (const float4*)g_h;
    float dd = g_dinv[node];
    float self = dd * dd;

    float4 hv = hb[(size_t)node * 32 + lane];
    float ax = hv.x * self, ay = hv.y * self, az = hv.z * self, aw = hv.w * self;

    int beg = g_off[node];
    int end = g_off[node + 1];
    int j = beg;

    for (; j + 4 <= end; j += 4) {
        int2 e0 = __ldg(g_csr + j);
        int2 e1 = __ldg(g_csr + j + 1);
        int2 e2 = __ldg(g_csr + j + 2);
        int2 e3 = __ldg(g_csr + j + 3);
        float4 v0 = hb[(size_t)e0.x * 32 + lane];
        float4 v1 = hb[(size_t)e1.x * 32 + lane];
        float4 v2 = hb[(size_t)e2.x * 32 + lane];
        float4 v3 = hb[(size_t)e3.x * 32 + lane];
        float n0 = __int_as_float(e0.y) * dd;
        float n1 = __int_as_float(e1.y) * dd;
        float n2 = __int_as_float(e2.y) * dd;
        float n3 = __int_as_float(e3.y) * dd;
        ax += v0.x * n0 + v1.x * n1 + v2.x * n2 + v3.x * n3;
        ay += v0.y * n0 + v1.y * n1 + v2.y * n2 + v3.y * n3;
        az += v0.z * n0 + v1.z * n1 + v2.z * n2 + v3.z * n3;
        aw += v0.w * n0 + v1.w * n1 + v2.w * n2 + v3.w * n3;
    }
    for (; j < end; j++) {
        int2 e0 = __ldg(g_csr + j);
        float4 v0 = hb[(size_t)e0.x * 32 + lane];
        float n0 = __int_as_float(e0.y) * dd;
        ax += v0.x * n0; ay += v0.y * n0; az += v0.z * n0; aw += v0.w * n0;
    }

    float4 bv = ((const float4*)b)[lane];
    ax += bv.x; ay += bv.y; az += bv.z; aw += bv.w;

    float slope = a[0];
    ax = ax >= 0.f ? ax : slope * ax;
    ay = ay >= 0.f ? ay : slope * ay;
    az = az >= 0.f ? az : slope * az;
    aw = aw >= 0.f ? aw : slope * aw;

    ((float4*)(out + (size_t)node * D))[lane] = make_float4(ax, ay, az, aw);
}

// ---------------------------------------------------------------------------
extern "C" void kernel_launch(void* const* d_in, const int* in_sizes, int n_in,
                              void* d_out, int out_size) {
    const float* x  = (const float*)d_in[0];
    const int*   ei = (const int*)d_in[1];
    const float* W  = (const float*)d_in[2];
    const float* b  = (const float*)d_in[3];
    const float* a  = (const float*)d_in[4];
    float* out = (float*)d_out;

    int n = in_sizes[0] / D;
    int e = in_sizes[1] / 2;
    const int* src = ei;
    const int* dst = ei + e;

    int nb = (n + 255) / 256;
    int eb = (e + 255) / 256;
    int sb = (n + 1023) / 1024;          // scan blocks (<=1024)

    k_pre<<<nb, 256>>>(W, n);
    k_hist<<<eb, 256>>>(dst, e);
    k_scanA<<<sb, 1024>>>(n);
    k_scanB<<<1, 1024>>>(sb);
    k_scanC<<<sb, 1024>>>(n, e);
    k_fill<<<eb, 256>>>(src, dst, e);

    const int gemm_smem = 3 * 128 * SK * 4;   // 55296 B
    cudaFuncSetAttribute(k_gemm, cudaFuncAttributeMaxDynamicSharedMemorySize, gemm_smem);
    k_gemm<<<(n + 127) / 128, 256, gemm_smem>>>(x, n);

    k_agg<<<(n * 32 + 255) / 256, 256>>>(b, a, out, n);
}